// round 11
// baseline (speedup 1.0000x reference)
#include <cuda_runtime.h>
#include <cstdint>

// ---------------------------------------------------------------------------
// out[b,co,y,x] = alpha[co] * sum_{ci,ky,kx} sign(x[..]) * sign(w[..])
// XNOR-popcount with CSA compression; 16/64 co on plain-POPC path (pipe blend);
// 2 output pixels per thread.
// ---------------------------------------------------------------------------
#define NB   32
#define CIN  64
#define COUT 64
#define HH   160
#define WW   160
#define HW   (HH*WW)          // 25600
#define H2   162
#define W2   162
#define PADWORDS (NB*H2*W2)   // 839808

#define ZMAX 8192
#define CO_CSA 48             // co [0,48) CSA path, [48,64) plain path

__device__ unsigned long long g_packed[PADWORDS];
__device__ unsigned long long g_pw[COUT*9];
__device__ float              g_alpha[COUT];
__device__ float2             g_coeff[9*COUT];
__device__ int                g_zero_count;
__device__ int                g_zero_list[ZMAX];

// ---------------------------------------------------------------------------
// Kernel 1: weight prep. 64 blocks (co) x 64 threads (ci). Ballot bit-pack.
// ---------------------------------------------------------------------------
__global__ __launch_bounds__(64) void prep_kernel(const float* __restrict__ w)
{
    __shared__ unsigned bl[2][9];
    __shared__ float red[2];
    __shared__ float salpha;
    __shared__ int S[9];
    int co = blockIdx.x, ci = threadIdx.x;
    if (co == 0 && ci == 0) g_zero_count = 0;
    int lane = ci & 31, wrp = ci >> 5;
    float sum = 0.f;
#pragma unroll
    for (int t = 0; t < 9; t++) {
        float v = w[(co*CIN + ci)*9 + t];
        float vc = fminf(fmaxf(v, -1.f), 1.f);
        sum += fabsf(vc);
        unsigned m = __ballot_sync(0xFFFFFFFFu, !(__float_as_uint(vc) >> 31));
        if (lane == 0) bl[wrp][t] = m;
    }
#pragma unroll
    for (int o = 16; o > 0; o >>= 1) sum += __shfl_down_sync(0xFFFFFFFFu, sum, o);
    if (lane == 0) red[wrp] = sum;
    __syncthreads();
    if (ci == 0) {
        float a = (red[0] + red[1]) * (1.f/576.f);
        salpha = a;
        g_alpha[co] = a;
    }
    if (ci < 9) {
        unsigned long long bits =
            (unsigned long long)bl[0][ci] | ((unsigned long long)bl[1][ci] << 32);
        g_pw[co*9 + ci] = bits;
        S[ci] = 64 - 2*__popcll(bits);
    }
    __syncthreads();
    if (ci < 9) {
        int cy = ci / 3, cx = ci % 3;
        int corr = 0;
#pragma unroll
        for (int t = 0; t < 9; t++) {
            int ky = t/3, kx = t%3;
            bool oob = (cy==0&&ky==0)||(cy==2&&ky==2)||(cx==0&&kx==0)||(cx==2&&kx==2);
            if (oob) corr += S[t];
        }
        float2 c;
        c.x = salpha * (float)(576 - corr);
        c.y = -2.f * salpha;
        g_coeff[ci*COUT + co] = c;
    }
}

// ---------------------------------------------------------------------------
// Kernel 2: pack activation signs into padded u64 words; record exact zeros.
// ---------------------------------------------------------------------------
__global__ void pack_kernel(const float* __restrict__ x)
{
    int idx = blockIdx.x * blockDim.x + threadIdx.x;
    if (idx >= PADWORDS) return;
    int b  = idx / (H2*W2);
    int r  = idx % (H2*W2);
    int y2 = r / W2;
    int x2 = r % W2;
    if (y2 == 0 || y2 == H2-1 || x2 == 0 || x2 == W2-1) {
        g_packed[idx] = 0ull;
        return;
    }
    int y = y2 - 1, xx = x2 - 1;
    const float* px = x + (long long)b*CIN*HW + y*WW + xx;

    unsigned long long word = 0ull;
#pragma unroll 8
    for (int ci = 0; ci < CIN; ci++) {
        float v = px[(long long)ci*HW];
        unsigned u = __float_as_uint(v);
        unsigned treated = (u >> 31) ^ 1u;
        if (!(u >> 31)) word |= (1ull << ci);
        if (v == 0.0f) {
            int slot = atomicAdd(&g_zero_count, 1);
            if (slot < ZMAX)
                g_zero_list[slot] = (b<<23) | (ci<<17) | (y<<9) | (xx<<1) | (int)treated;
        }
    }
    g_packed[idx] = word;
}

// ---------------------------------------------------------------------------
// CSA helpers
// ---------------------------------------------------------------------------
__device__ __forceinline__ void FA(unsigned a, unsigned b, unsigned c,
                                   unsigned& s, unsigned& cy)
{
    s  = a ^ b ^ c;
    cy = (a & b) | (c & (a | b));
}

__device__ __forceinline__ int popc9(const unsigned* v)
{
    unsigned s0,c0,s1,c1,s2,c2,s3,c3,s4,c4;
    FA(v[0], v[1], v[2], s0, c0);
    FA(v[3], v[4], v[5], s1, c1);
    FA(v[6], v[7], v[8], s2, c2);
    FA(s0, s1, s2, s3, c3);
    FA(c0, c1, c2, s4, c4);
    return __popc(s3) + 2*(__popc(c3) + __popc(s4)) + 4*__popc(c4);
}

// one pixel, CSA path: taps from column window [cbase, cbase+2]
__device__ __forceinline__ int pix_csa(const unsigned xl[3][4], const unsigned xh[3][4],
                                       int cbase, const unsigned* wv)
{
    unsigned vl[9], vh[9];
#pragma unroll
    for (int ky = 0; ky < 3; ky++)
#pragma unroll
        for (int kx = 0; kx < 3; kx++) {
            int t = ky*3 + kx;
            vl[t] = xl[ky][cbase+kx] ^ wv[2*t];
            vh[t] = xh[ky][cbase+kx] ^ wv[2*t+1];
        }
    return popc9(vl) + popc9(vh);
}

// one pixel, plain path (POPC-heavy, alu-light)
__device__ __forceinline__ int pix_plain(const unsigned xl[3][4], const unsigned xh[3][4],
                                         int cbase, const unsigned* wv)
{
    int p[9];
#pragma unroll
    for (int ky = 0; ky < 3; ky++)
#pragma unroll
        for (int kx = 0; kx < 3; kx++) {
            int t = ky*3 + kx;
            p[t] = __popc(xl[ky][cbase+kx] ^ wv[2*t])
                 + __popc(xh[ky][cbase+kx] ^ wv[2*t+1]);
        }
    return ((p[0]+p[1]) + (p[2]+p[3])) + ((p[4]+p[5]) + (p[6]+p[7])) + p[8];
}

// ---------------------------------------------------------------------------
// Kernel 3: main conv. Thread = TWO adjacent output pixels (x even, x+1).
// ---------------------------------------------------------------------------
__global__ __launch_bounds__(256, 2) void conv_kernel(float* __restrict__ out)
{
    __shared__ __align__(16) unsigned swv[COUT*20];  // [co][20]: (lo,hi) x 9 taps + pad
    __shared__ float2 scoef[9*COUT];

    int tid = threadIdx.x;
    for (int i = tid; i < COUT*9; i += 256) {
        int co = i / 9, t = i % 9;
        unsigned long long bword = g_pw[i];
        swv[co*20 + 2*t]     = (unsigned)bword;
        swv[co*20 + 2*t + 1] = (unsigned)(bword >> 32);
    }
    for (int i = tid; i < 9*COUT; i += 256) scoef[i] = g_coeff[i];
    __syncthreads();

    int thr = blockIdx.x * 256 + tid;        // 0 .. 409599
    int p   = thr * 2;                       // even pixel index
    int b   = p / HW;
    int r   = p % HW;
    int y   = r / WW;
    int x0  = r % WW;                        // even, pair = (x0, x0+1) same row

    // 12 tap words: rows y+ky, padded cols x0 .. x0+3
    const uint2* pp = (const uint2*)g_packed + ((long long)b*H2 + y)*W2 + x0;
    unsigned xl[3][4], xh[3][4];
#pragma unroll
    for (int ky = 0; ky < 3; ky++)
#pragma unroll
        for (int c = 0; c < 4; c++) {
            uint2 v = pp[ky*W2 + c];
            xl[ky][c] = v.x;
            xh[ky][c] = v.y;
        }

    int cy  = (y == 0) ? 0 : ((y == HH-1) ? 2 : 1);
    int cx0 = (x0 == 0) ? 0 : 1;             // x0 even -> never 159
    int cx1 = (x0+1 == WW-1) ? 2 : 1;
    const float2* cf0 = scoef + (cy*3 + cx0) * COUT;
    const float2* cf1 = scoef + (cy*3 + cx1) * COUT;

    float* outp = out + ((long long)b*COUT)*HW + y*WW + x0;

#pragma unroll 2
    for (int co = 0; co < CO_CSA; co++) {
        unsigned wv[20];
#pragma unroll
        for (int k = 0; k < 5; k++)
            ((uint4*)wv)[k] = ((const uint4*)(swv + co*20))[k];
        int acc0 = pix_csa(xl, xh, 0, wv);
        int acc1 = pix_csa(xl, xh, 1, wv);
        float2 c0 = cf0[co], c1 = cf1[co];
        float2 st;
        st.x = fmaf(c0.y, (float)acc0, c0.x);
        st.y = fmaf(c1.y, (float)acc1, c1.x);
        *(float2*)(outp + (long long)co*HW) = st;
    }
#pragma unroll 2
    for (int co = CO_CSA; co < COUT; co++) {
        unsigned wv[20];
#pragma unroll
        for (int k = 0; k < 5; k++)
            ((uint4*)wv)[k] = ((const uint4*)(swv + co*20))[k];
        int acc0 = pix_plain(xl, xh, 0, wv);
        int acc1 = pix_plain(xl, xh, 1, wv);
        float2 c0 = cf0[co], c1 = cf1[co];
        float2 st;
        st.x = fmaf(c0.y, (float)acc0, c0.x);
        st.y = fmaf(c1.y, (float)acc1, c1.x);
        *(float2*)(outp + (long long)co*HW) = st;
    }
}

// ---------------------------------------------------------------------------
// Kernel 4: fixup for exact-zero activations (sign(0)=0).
// ---------------------------------------------------------------------------
__global__ void fixup_kernel(float* __restrict__ out)
{
    int cnt = g_zero_count;
    if (cnt > ZMAX) cnt = ZMAX;
    int total = cnt * COUT * 9;
    for (int i = blockIdx.x * blockDim.x + threadIdx.x; i < total;
         i += gridDim.x * blockDim.x) {
        int zi  = i / (COUT*9);
        int rem = i % (COUT*9);
        int co  = rem / 9;
        int t   = rem % 9;
        int e   = g_zero_list[zi];
        int b   = (e >> 23) & 31;
        int ci  = (e >> 17) & 63;
        int y   = (e >> 9)  & 255;
        int xx  = (e >> 1)  & 255;
        int ts  = e & 1;
        int ky = t / 3, kx = t % 3;
        int yo = y - ky + 1;
        int xo = xx - kx + 1;
        if (yo < 0 || yo >= HH || xo < 0 || xo >= WW) continue;
        int wbit = (int)((g_pw[co*9 + t] >> ci) & 1ull);
        float ws  = wbit ? 1.0f : -1.0f;
        float tsf = ts   ? 1.0f : -1.0f;
        atomicAdd(&out[(((long long)b*COUT + co)*HH + yo)*WW + xo],
                  -g_alpha[co] * ws * tsf);
    }
}

// ---------------------------------------------------------------------------
extern "C" void kernel_launch(void* const* d_in, const int* in_sizes, int n_in,
                              void* d_out, int out_size)
{
    const float* x = (const float*)d_in[0];   // [32,64,160,160]
    const float* w = (const float*)d_in[1];   // [64,64,3,3]
    float* out = (float*)d_out;               // [32,64,160,160]

    prep_kernel<<<64, 64>>>(w);

    int packBlocks = (PADWORDS + 255) / 256;
    pack_kernel<<<packBlocks, 256>>>(x);

    conv_kernel<<<(NB*HW)/512, 256>>>(out);

    fixup_kernel<<<64, 256>>>(out);
}